// round 5
// baseline (speedup 1.0000x reference)
#include <cuda_runtime.h>
#include <math.h>

// Problem constants (fixed shapes from setup_inputs)
#define D 64
#define R 64
#define T 4096
#define B 8
#define NTOK (B * T)                  // 32768
#define STRENGTH 0.1f
#define SC 0.17677669529663687f       // sqrt(2/64)

#define K1_BLOCKS 512                 // 8 batches * 64 token-chunks of 64
#define CHUNKS_PER_BATCH 64
#define STRIDE 68                     // smem row stride (floats): 16B-aligned rows

// dynamic smem layout (floats)
#define OFF_W   0                     // [128][68] combined weights
#define OFF_C   (128 * STRIDE)        // [64][68]  coords
#define OFF_P   (192 * STRIDE)        // [16][64]  per-token-group partials
#define OFF_B1  (OFF_P + 1024)        // [64]
#define OFF_W2  (OFF_B1 + 64)         // [64]
#define OFF_BR  (OFF_W2 + 64)         // [64]
#define SMEM_FLOATS (OFF_BR + 64)
#define SMEM_BYTES  (SMEM_FLOATS * 4) // 57088 B -> 4 CTAs/SM fits in 228KB

// Scratch (device globals — no allocation)
__device__ float g_phi[(size_t)NTOK * R];        // 8 MB
__device__ float g_partial[K1_BLOCKS * R];
__device__ float g_grav[NTOK];                   // includes STRENGTH factor

// ---------------------------------------------------------------------------
// K1: two-phase tiled GEMM (16 accs/phase) with fully fused epilogue.
// Block: 256 threads, 64 tokens. Thread: 4 tokens (tg) x 4 rows (rg+16i).
// ---------------------------------------------------------------------------
__global__ __launch_bounds__(256, 4) void k1_phi_mass(
    const float* __restrict__ coords, const float* __restrict__ w1,
    const float* __restrict__ b1, const float* __restrict__ w2,
    const float* __restrict__ b2, const float* __restrict__ W,
    const float* __restrict__ bR)
{
    extern __shared__ float sm[];
    float* s_w    = sm + OFF_W;    // rows 0-63 = w1[r][k], rows 64-127 = W^T[r][k]
    float* s_c    = sm + OFF_C;
    float* s_part = sm + OFF_P;
    float* s_b1   = sm + OFF_B1;
    float* s_w2   = sm + OFF_W2;
    float* s_bR   = sm + OFF_BR;

    const int tid = threadIdx.x;
    const int bb = blockIdx.x >> 6, chunk = blockIdx.x & 63;
    const int tokBase = bb * T + chunk * 64;

    // --- stage weights + coords ---
    for (int idx = tid; idx < 4096; idx += 256) {
        int r = idx >> 6, k = idx & 63;
        s_w[r * STRIDE + k] = w1[idx];                 // w1[r][k]
    }
    for (int idx = tid; idx < 4096; idx += 256) {
        int k = idx >> 6, r = idx & 63;
        s_w[(64 + r) * STRIDE + k] = W[idx];           // W[k][r] -> row 64+r
    }
    for (int idx = tid; idx < 4096; idx += 256) {
        int t = idx >> 6, k = idx & 63;
        s_c[t * STRIDE + k] = coords[(size_t)(tokBase + t) * D + k];
    }
    if (tid < 64) { s_b1[tid] = b1[tid]; s_w2[tid] = w2[tid]; s_bR[tid] = bR[tid]; }
    __syncthreads();

    const int tg = tid >> 4;       // 0..15 : tokens tg*4 .. tg*4+3
    const int rg = tid & 15;       // 0..15 : rows rg + 16*i, i=0..3
    const float* cb = s_c + (tg * 4) * STRIDE;
    const float b2v = __ldg(b2);

    // =========================== PHASE A: mass ===========================
    float mass[4];
    {
        float acc[4][4];
        #pragma unroll
        for (int j = 0; j < 4; ++j)
            #pragma unroll
            for (int i = 0; i < 4; ++i) acc[j][i] = 0.f;

        const float* wb = s_w + rg * STRIDE;           // w1 rows rg+16i
        #pragma unroll
        for (int k4 = 0; k4 < 16; ++k4) {
            float4 c[4], w[4];
            #pragma unroll
            for (int j = 0; j < 4; ++j)
                c[j] = *(const float4*)(cb + j * STRIDE + k4 * 4);
            #pragma unroll
            for (int i = 0; i < 4; ++i)
                w[i] = *(const float4*)(wb + i * 16 * STRIDE + k4 * 4);
            #pragma unroll
            for (int j = 0; j < 4; ++j)
                #pragma unroll
                for (int i = 0; i < 4; ++i) {
                    acc[j][i] = fmaf(c[j].x, w[i].x, acc[j][i]);
                    acc[j][i] = fmaf(c[j].y, w[i].y, acc[j][i]);
                    acc[j][i] = fmaf(c[j].z, w[i].z, acc[j][i]);
                    acc[j][i] = fmaf(c[j].w, w[i].w, acc[j][i]);
                }
        }

        // relu + partial dot with w2 over this thread's 4 rows, then reduce
        // across the 16-lane token-group (xor 8/4/2/1 stay within each half).
        #pragma unroll
        for (int j = 0; j < 4; ++j) {
            float mp = 0.f;
            #pragma unroll
            for (int i = 0; i < 4; ++i) {
                const int row = rg + i * 16;
                const float h = fmaxf(acc[j][i] + s_b1[row], 0.f);
                mp = fmaf(h, s_w2[row], mp);
            }
            mp += __shfl_xor_sync(0xffffffffu, mp, 8);
            mp += __shfl_xor_sync(0xffffffffu, mp, 4);
            mp += __shfl_xor_sync(0xffffffffu, mp, 2);
            mp += __shfl_xor_sync(0xffffffffu, mp, 1);
            const float x = mp + b2v;
            mass[j] = fmaxf(x, 0.f) + __logf(1.f + __expf(-fabsf(x)));
        }
    }

    // ============================ PHASE B: phi ===========================
    {
        float acc[4][4];
        #pragma unroll
        for (int j = 0; j < 4; ++j)
            #pragma unroll
            for (int i = 0; i < 4; ++i) acc[j][i] = 0.f;

        const float* wb = s_w + (64 + rg) * STRIDE;    // W^T rows rg+16i
        #pragma unroll
        for (int k4 = 0; k4 < 16; ++k4) {
            float4 c[4], w[4];
            #pragma unroll
            for (int j = 0; j < 4; ++j)
                c[j] = *(const float4*)(cb + j * STRIDE + k4 * 4);
            #pragma unroll
            for (int i = 0; i < 4; ++i)
                w[i] = *(const float4*)(wb + i * 16 * STRIDE + k4 * 4);
            #pragma unroll
            for (int j = 0; j < 4; ++j)
                #pragma unroll
                for (int i = 0; i < 4; ++i) {
                    acc[j][i] = fmaf(c[j].x, w[i].x, acc[j][i]);
                    acc[j][i] = fmaf(c[j].y, w[i].y, acc[j][i]);
                    acc[j][i] = fmaf(c[j].z, w[i].z, acc[j][i]);
                    acc[j][i] = fmaf(c[j].w, w[i].w, acc[j][i]);
                }
        }

        // phi -> g_phi, accumulate mass-weighted partial per row
        float part[4] = {0.f, 0.f, 0.f, 0.f};
        #pragma unroll
        for (int j = 0; j < 4; ++j) {
            const size_t gbase = (size_t)(tokBase + tg * 4 + j) * R;
            #pragma unroll
            for (int i = 0; i < 4; ++i) {
                const int row = rg + i * 16;
                const float ph = SC * __cosf(acc[j][i] + s_bR[row]);
                g_phi[gbase + row] = ph;
                part[i] = fmaf(mass[j], ph, part[i]);
            }
        }
        #pragma unroll
        for (int i = 0; i < 4; ++i)
            s_part[tg * 64 + rg + i * 16] = part[i];
    }
    __syncthreads();

    if (tid < 64) {
        float s = 0.f;
        #pragma unroll
        for (int t = 0; t < 16; ++t) s += s_part[t * 64 + tid];
        g_partial[blockIdx.x * 64 + tid] = s;
    }
}

// ---------------------------------------------------------------------------
// K3: fused phisum reduce + grav[t] = STRENGTH * dot(phi[t], phi_sum[batch])
// ---------------------------------------------------------------------------
__global__ __launch_bounds__(256) void k3_grav()
{
    __shared__ float s_ps[64];
    const int tid = threadIdx.x, lane = tid & 31, warp = tid >> 5;
    const int bb = blockIdx.x >> 6, chunk = blockIdx.x & 63;

    if (tid < 64) {
        float s = 0.f;
        #pragma unroll
        for (int c = 0; c < CHUNKS_PER_BATCH; ++c)
            s += g_partial[(bb * CHUNKS_PER_BATCH + c) * 64 + tid];
        s_ps[tid] = s;
    }
    __syncthreads();

    const int tokBase = bb * T + chunk * 64 + warp * 8;
    const float ps0 = s_ps[lane];
    const float ps1 = s_ps[lane + 32];

    #pragma unroll
    for (int g = 0; g < 2; ++g) {
        const int t0 = tokBase + g * 4;
        float v[4];
        #pragma unroll
        for (int j = 0; j < 4; ++j) {
            const float* ph = g_phi + (size_t)(t0 + j) * R;
            v[j] = fmaf(ph[lane], ps0, ph[lane + 32] * ps1);
        }
        #pragma unroll
        for (int s = 16; s >= 1; s >>= 1) {
            #pragma unroll
            for (int j = 0; j < 4; ++j)
                v[j] += __shfl_xor_sync(0xffffffffu, v[j], s);
        }
        if (lane == 0) {
            g_grav[t0 + 0] = STRENGTH * v[0];
            g_grav[t0 + 1] = STRENGTH * v[1];
            g_grav[t0 + 2] = STRENGTH * v[2];
            g_grav[t0 + 3] = STRENGTH * v[3];
        }
    }
}

// ---------------------------------------------------------------------------
// K4: the roofline — 1 GiB stream of G with fused diagonal add.
// ---------------------------------------------------------------------------
__global__ __launch_bounds__(256) void k4_copy(const float4* __restrict__ G4,
                                               float4* __restrict__ O4)
{
    const unsigned tile = blockIdx.x;
    const size_t base = (size_t)tile * 1024;
    const float gv = g_grav[tile];               // uniform per block

    float4 v[4];
    #pragma unroll
    for (int k = 0; k < 4; ++k)
        v[k] = __ldcs(G4 + base + k * 256u + threadIdx.x);

    #pragma unroll
    for (int k = 0; k < 4; ++k) {
        const unsigned within = k * 256u + threadIdx.x;
        const int i  = (int)(within >> 4);
        const int j0 = (int)((within & 15u) << 2);
        const int d  = i - j0;
        if ((unsigned)d < 4u) {
            if      (d == 0) v[k].x += gv;
            else if (d == 1) v[k].y += gv;
            else if (d == 2) v[k].z += gv;
            else             v[k].w += gv;
        }
        __stcs(O4 + base + within, v[k]);
    }
}

// ---------------------------------------------------------------------------
extern "C" void kernel_launch(void* const* d_in, const int* in_sizes, int n_in,
                              void* d_out, int out_size)
{
    const float* G      = (const float*)d_in[0];
    const float* coords = (const float*)d_in[1];
    const float* w1     = (const float*)d_in[2];
    const float* b1     = (const float*)d_in[3];
    const float* w2     = (const float*)d_in[4];
    const float* b2     = (const float*)d_in[5];
    const float* W      = (const float*)d_in[6];
    const float* bR     = (const float*)d_in[7];
    float* out = (float*)d_out;

    cudaFuncSetAttribute(k1_phi_mass,
                         cudaFuncAttributeMaxDynamicSharedMemorySize, SMEM_BYTES);

    k1_phi_mass<<<K1_BLOCKS, 256, SMEM_BYTES>>>(coords, w1, b1, w2, b2, W, bR);
    k3_grav<<<K1_BLOCKS, 256>>>();
    k4_copy<<<NTOK, 256>>>((const float4*)G, (float4*)out);
}

// round 6
// speedup vs baseline: 1.4304x; 1.4304x over previous
#include <cuda_runtime.h>
#include <math.h>

// Problem constants (fixed shapes from setup_inputs)
#define D 64
#define R 64
#define T 4096
#define B 8
#define NTOK (B * T)                  // 32768
#define STRENGTH 0.1f
#define SC 0.17677669529663687f       // sqrt(2/64)

#define K1_BLOCKS 256                 // 8 batches * 32 chunks of 128 tokens
#define K1_CHUNKS 32                  // per batch (128 tokens each)
#define K3_BLOCKS 512                 // 8 batches * 64 chunks of 64 tokens
#define STRIDE 68                     // smem row stride (floats): 16B-aligned

// dynamic smem layout (floats)
#define OFF_W   0                     // [128][68] combined weights (persistent)
#define OFF_C   (128 * STRIDE)        // [64][68]  coords (per sub-pass)
#define OFF_P   (192 * STRIDE)        // [16][64]  per-token-group partials
#define OFF_B1  (OFF_P + 1024)        // [64]
#define OFF_W2  (OFF_B1 + 64)         // [64]
#define OFF_BR  (OFF_W2 + 64)         // [64]
#define SMEM_FLOATS (OFF_BR + 64)
#define SMEM_BYTES  (SMEM_FLOATS * 4) // 57088 B -> 2 CTAs/SM

// Scratch (device globals — no allocation)
__device__ float g_phi[(size_t)NTOK * R];        // 8 MB
__device__ float g_partial[K1_BLOCKS * R];
__device__ float g_grav[NTOK];                   // includes STRENGTH factor

// ---------------------------------------------------------------------------
// K1: tiled GEMM coords @ [w1^T | W], 128 tokens/block in two sub-passes.
// Thread tile: 4 tokens (tg) x 8 rows (rg + 16*i; i<4 = w1, i>=4 = W).
// Epilogue is register/shfl-only; weights stay resident across sub-passes.
// ---------------------------------------------------------------------------
__global__ __launch_bounds__(256) void k1_phi_mass(
    const float* __restrict__ coords, const float* __restrict__ w1,
    const float* __restrict__ b1, const float* __restrict__ w2,
    const float* __restrict__ b2, const float* __restrict__ W,
    const float* __restrict__ bR)
{
    extern __shared__ float sm[];
    float* s_w    = sm + OFF_W;    // rows 0-63 = w1[r][k], rows 64-127 = W^T[r][k]
    float* s_c    = sm + OFF_C;
    float* s_part = sm + OFF_P;
    float* s_b1   = sm + OFF_B1;
    float* s_w2   = sm + OFF_W2;
    float* s_bR   = sm + OFF_BR;

    const int tid = threadIdx.x;
    const int bb = blockIdx.x >> 5, chunk = blockIdx.x & 31;
    const int tokBase0 = bb * T + chunk * 128;

    // --- stage weights (persistent for both sub-passes) ---
    for (int idx = tid; idx < 4096; idx += 256) {
        int r = idx >> 6, k = idx & 63;
        s_w[r * STRIDE + k] = w1[idx];                 // w1[r][k]
    }
    for (int idx = tid; idx < 4096; idx += 256) {
        int k = idx >> 6, r = idx & 63;
        s_w[(64 + r) * STRIDE + k] = W[idx];           // W[k][r] -> row 64+r
    }
    if (tid < 64) { s_b1[tid] = b1[tid]; s_w2[tid] = w2[tid]; s_bR[tid] = bR[tid]; }

    const int tg = tid >> 4;       // 0..15 : tokens tg*4 .. tg*4+3
    const int rg = tid & 15;       // 0..15 : rows rg + 16*i
    const float b2v = __ldg(b2);
    const float* cb = s_c + (tg * 4) * STRIDE;
    const float* wb = s_w + rg * STRIDE;

    float part[4] = {0.f, 0.f, 0.f, 0.f};   // mass-weighted phi partials

    for (int sub = 0; sub < 2; ++sub) {
        const int tokBase = tokBase0 + sub * 64;

        // --- stage this sub-pass's 64 tokens of coords ---
        __syncthreads();            // previous pass's readers done
        for (int idx = tid; idx < 4096; idx += 256) {
            int t = idx >> 6, k = idx & 63;
            s_c[t * STRIDE + k] = coords[(size_t)(tokBase + t) * D + k];
        }
        __syncthreads();

        // --- GEMM: 4 tokens x 8 rows ---
        float acc[4][8];
        #pragma unroll
        for (int j = 0; j < 4; ++j)
            #pragma unroll
            for (int i = 0; i < 8; ++i) acc[j][i] = 0.f;

        #pragma unroll 4
        for (int k4 = 0; k4 < 16; ++k4) {
            float4 c[4], w[8];
            #pragma unroll
            for (int j = 0; j < 4; ++j)
                c[j] = *(const float4*)(cb + j * STRIDE + k4 * 4);
            #pragma unroll
            for (int i = 0; i < 8; ++i)
                w[i] = *(const float4*)(wb + i * 16 * STRIDE + k4 * 4);
            #pragma unroll
            for (int j = 0; j < 4; ++j)
                #pragma unroll
                for (int i = 0; i < 8; ++i) {
                    acc[j][i] = fmaf(c[j].x, w[i].x, acc[j][i]);
                    acc[j][i] = fmaf(c[j].y, w[i].y, acc[j][i]);
                    acc[j][i] = fmaf(c[j].z, w[i].z, acc[j][i]);
                    acc[j][i] = fmaf(c[j].w, w[i].w, acc[j][i]);
                }
        }

        // --- epilogue (registers + shfl only) ---
        // mass: 16 threads of group tg collectively hold all 64 w1 rows.
        #pragma unroll
        for (int j = 0; j < 4; ++j) {
            float mp = 0.f;
            #pragma unroll
            for (int i = 0; i < 4; ++i) {
                const int row = rg + i * 16;
                const float h = fmaxf(acc[j][i] + s_b1[row], 0.f);
                mp = fmaf(h, s_w2[row], mp);
            }
            mp += __shfl_xor_sync(0xffffffffu, mp, 8);
            mp += __shfl_xor_sync(0xffffffffu, mp, 4);
            mp += __shfl_xor_sync(0xffffffffu, mp, 2);
            mp += __shfl_xor_sync(0xffffffffu, mp, 1);
            const float x = mp + b2v;
            const float mass = fmaxf(x, 0.f) + __logf(1.f + __expf(-fabsf(x)));

            const size_t gbase = (size_t)(tokBase + tg * 4 + j) * R;
            #pragma unroll
            for (int i = 0; i < 4; ++i) {
                const int row = rg + i * 16;
                const float ph = SC * __cosf(acc[j][i + 4] + s_bR[row]);
                g_phi[gbase + row] = ph;
                part[i] = fmaf(mass, ph, part[i]);
            }
        }
    }

    __syncthreads();
    #pragma unroll
    for (int i = 0; i < 4; ++i)
        s_part[tg * 64 + rg + i * 16] = part[i];
    __syncthreads();

    if (tid < 64) {
        float s = 0.f;
        #pragma unroll
        for (int t = 0; t < 16; ++t) s += s_part[t * 64 + tid];
        g_partial[blockIdx.x * 64 + tid] = s;
    }
}

// ---------------------------------------------------------------------------
// K3: fused phisum reduce + grav[t] = STRENGTH * dot(phi[t], phi_sum[batch])
// ---------------------------------------------------------------------------
__global__ __launch_bounds__(256) void k3_grav()
{
    __shared__ float s_ps[64];
    const int tid = threadIdx.x, lane = tid & 31, warp = tid >> 5;
    const int bb = blockIdx.x >> 6, chunk = blockIdx.x & 63;

    if (tid < 64) {
        float s = 0.f;
        #pragma unroll
        for (int c = 0; c < K1_CHUNKS; ++c)
            s += g_partial[(bb * K1_CHUNKS + c) * 64 + tid];
        s_ps[tid] = s;
    }
    __syncthreads();

    const int tokBase = bb * T + chunk * 64 + warp * 8;
    const float ps0 = s_ps[lane];
    const float ps1 = s_ps[lane + 32];

    #pragma unroll
    for (int g = 0; g < 2; ++g) {
        const int t0 = tokBase + g * 4;
        float v[4];
        #pragma unroll
        for (int j = 0; j < 4; ++j) {
            const float* ph = g_phi + (size_t)(t0 + j) * R;
            v[j] = fmaf(ph[lane], ps0, ph[lane + 32] * ps1);
        }
        #pragma unroll
        for (int s = 16; s >= 1; s >>= 1) {
            #pragma unroll
            for (int j = 0; j < 4; ++j)
                v[j] += __shfl_xor_sync(0xffffffffu, v[j], s);
        }
        if (lane == 0) {
            g_grav[t0 + 0] = STRENGTH * v[0];
            g_grav[t0 + 1] = STRENGTH * v[1];
            g_grav[t0 + 2] = STRENGTH * v[2];
            g_grav[t0 + 3] = STRENGTH * v[3];
        }
    }
}

// ---------------------------------------------------------------------------
// K4: the roofline — 1 GiB stream of G with fused diagonal add.
// ---------------------------------------------------------------------------
__global__ __launch_bounds__(256) void k4_copy(const float4* __restrict__ G4,
                                               float4* __restrict__ O4)
{
    const unsigned tile = blockIdx.x;
    const size_t base = (size_t)tile * 1024;
    const float gv = g_grav[tile];               // uniform per block

    float4 v[4];
    #pragma unroll
    for (int k = 0; k < 4; ++k)
        v[k] = __ldcs(G4 + base + k * 256u + threadIdx.x);

    #pragma unroll
    for (int k = 0; k < 4; ++k) {
        const unsigned within = k * 256u + threadIdx.x;
        const int i  = (int)(within >> 4);
        const int j0 = (int)((within & 15u) << 2);
        const int d  = i - j0;
        if ((unsigned)d < 4u) {
            if      (d == 0) v[k].x += gv;
            else if (d == 1) v[k].y += gv;
            else if (d == 2) v[k].z += gv;
            else             v[k].w += gv;
        }
        __stcs(O4 + base + within, v[k]);
    }
}

// ---------------------------------------------------------------------------
extern "C" void kernel_launch(void* const* d_in, const int* in_sizes, int n_in,
                              void* d_out, int out_size)
{
    const float* G      = (const float*)d_in[0];
    const float* coords = (const float*)d_in[1];
    const float* w1     = (const float*)d_in[2];
    const float* b1     = (const float*)d_in[3];
    const float* w2     = (const float*)d_in[4];
    const float* b2     = (const float*)d_in[5];
    const float* W      = (const float*)d_in[6];
    const float* bR     = (const float*)d_in[7];
    float* out = (float*)d_out;

    cudaFuncSetAttribute(k1_phi_mass,
                         cudaFuncAttributeMaxDynamicSharedMemorySize, SMEM_BYTES);

    k1_phi_mass<<<K1_BLOCKS, 256, SMEM_BYTES>>>(coords, w1, b1, w2, b2, W, bR);
    k3_grav<<<K3_BLOCKS, 256>>>();
    k4_copy<<<NTOK, 256>>>((const float4*)G, (float4*)out);
}